// round 2
// baseline (speedup 1.0000x reference)
#include <cuda_runtime.h>
#include <math.h>

// Problem constants
constexpr int Bb   = 8;
constexpr int Tt   = 4096;
constexpr int DIN  = 1024;
constexpr int HH   = 2048;
constexpr int Mrows = Bb * Tt;  // 32768

// Scratch: u (later overwritten by p = h*gate) and gate. 256 MB each.
__device__ float g_u[(size_t)Mrows * HH];
__device__ float g_g[(size_t)Mrows * HH];

// ---------------------------------------------------------------------------
// C[m,n] = sum_k A[m,k] * Bw[n,k] + bias[n]   (NT GEMM, both row-major, K contig)
// ACT: 0 = none, 1 = sigmoid
// Tiling: 128x128 block, BK=16, 8x8 per thread, 256 threads.
// M, N, K all assumed multiples of 128/128/16 (true for this problem).
// ---------------------------------------------------------------------------
template <int ACT>
__global__ __launch_bounds__(256) void gemm_nt_kernel(
    const float* __restrict__ A, const float* __restrict__ Bw,
    const float* __restrict__ bias, float* __restrict__ C,
    int N, int K) {
  __shared__ float As[16][128 + 4];
  __shared__ float Bs[16][128 + 4];

  const int m0 = blockIdx.y * 128;
  const int n0 = blockIdx.x * 128;
  const int tid = threadIdx.x;
  const int tx = tid & 15;       // N sub-tile
  const int ty = tid >> 4;       // M sub-tile
  const int lr = tid >> 2;       // load row 0..63
  const int lc = (tid & 3) << 2; // load k-offset 0,4,8,12

  float acc[8][8];
#pragma unroll
  for (int i = 0; i < 8; i++)
#pragma unroll
    for (int j = 0; j < 8; j++) acc[i][j] = 0.f;

  for (int k0 = 0; k0 < K; k0 += 16) {
#pragma unroll
    for (int rr = 0; rr < 2; rr++) {
      int row = lr + rr * 64;
      float4 va = *reinterpret_cast<const float4*>(
          &A[(size_t)(m0 + row) * K + k0 + lc]);
      As[lc + 0][row] = va.x; As[lc + 1][row] = va.y;
      As[lc + 2][row] = va.z; As[lc + 3][row] = va.w;
      float4 vb = *reinterpret_cast<const float4*>(
          &Bw[(size_t)(n0 + row) * K + k0 + lc]);
      Bs[lc + 0][row] = vb.x; Bs[lc + 1][row] = vb.y;
      Bs[lc + 2][row] = vb.z; Bs[lc + 3][row] = vb.w;
    }
    __syncthreads();

#pragma unroll
    for (int kk = 0; kk < 16; kk++) {
      float ra[8], rb[8];
#pragma unroll
      for (int i = 0; i < 8; i++) ra[i] = As[kk][ty * 8 + i];
#pragma unroll
      for (int j = 0; j < 8; j++) rb[j] = Bs[kk][tx * 8 + j];
#pragma unroll
      for (int i = 0; i < 8; i++)
#pragma unroll
        for (int j = 0; j < 8; j++)
          acc[i][j] = fmaf(ra[i], rb[j], acc[i][j]);
    }
    __syncthreads();
  }

#pragma unroll
  for (int i = 0; i < 8; i++) {
    int m = m0 + ty * 8 + i;
#pragma unroll
    for (int j = 0; j < 8; j++) {
      int n = n0 + tx * 8 + j;
      float v = acc[i][j] + bias[n];
      if (ACT == 1) v = 1.f / (1.f + expf(-v));
      C[(size_t)m * N + n] = v;
    }
  }
}

// ---------------------------------------------------------------------------
// Diagonal scan h_t = a*h_{t-1} + u_t, then p_t = h_t * gate_t, written
// in place over u. One thread per (b,h); loads coalesced across h.
// ---------------------------------------------------------------------------
__global__ __launch_bounds__(256) void scan_gate_kernel(
    const float* __restrict__ log_a) {
  int idx = blockIdx.x * blockDim.x + threadIdx.x;  // 0 .. B*H-1
  int b = idx / HH;
  int h = idx % HH;
  float a = 1.f / (1.f + expf(-log_a[h]));
  float hs = 0.f;

  float* up = g_u + (size_t)b * Tt * HH + h;        // aliases output p
  const float* gp = g_g + (size_t)b * Tt * HH + h;

  for (int t0 = 0; t0 < Tt; t0 += 16) {
    float uu[16], gg[16];
#pragma unroll
    for (int i = 0; i < 16; i++) {
      uu[i] = up[(size_t)(t0 + i) * HH];
      gg[i] = gp[(size_t)(t0 + i) * HH];
    }
#pragma unroll
    for (int i = 0; i < 16; i++) {
      hs = fmaf(a, hs, uu[i]);
      up[(size_t)(t0 + i) * HH] = hs * gg[i];
    }
  }
}

// ---------------------------------------------------------------------------
// Launch: u-GEMM, gate-GEMM, scan+gate, output GEMM. Default stream serializes.
// ---------------------------------------------------------------------------
extern "C" void kernel_launch(void* const* d_in, const int* in_sizes, int n_in,
                              void* d_out, int out_size) {
  const float* x     = (const float*)d_in[0];
  const float* Wi    = (const float*)d_in[1];
  const float* bi    = (const float*)d_in[2];
  const float* Wg    = (const float*)d_in[3];
  const float* bg    = (const float*)d_in[4];
  const float* Wo    = (const float*)d_in[5];
  const float* bo    = (const float*)d_in[6];
  const float* log_a = (const float*)d_in[7];
  float* y = (float*)d_out;

  float* u_ptr = nullptr;
  float* g_ptr = nullptr;
  cudaGetSymbolAddress((void**)&u_ptr, g_u);
  cudaGetSymbolAddress((void**)&g_ptr, g_g);

  dim3 blk(256);
  dim3 grd_ug(HH / 128, Mrows / 128);   // (16, 256)
  gemm_nt_kernel<0><<<grd_ug, blk>>>(x, Wi, bi, u_ptr, HH, DIN);
  gemm_nt_kernel<1><<<grd_ug, blk>>>(x, Wg, bg, g_ptr, HH, DIN);

  scan_gate_kernel<<<(Bb * HH) / 256, 256>>>(log_a);

  dim3 grd_y(DIN / 128, Mrows / 128);   // (8, 256)
  gemm_nt_kernel<0><<<grd_y, blk>>>(u_ptr, Wo, bo, y, DIN, HH);
}

// round 4
// speedup vs baseline: 1.7992x; 1.7992x over previous
#include <cuda_runtime.h>
#include <cuda_bf16.h>
#include <math.h>
#include <stdint.h>

// Problem constants
constexpr int Bb   = 8;
constexpr int Tt   = 4096;
constexpr int DIN  = 1024;
constexpr int HH   = 2048;
constexpr int Mrows = Bb * Tt;  // 32768

// Scratch: u (later overwritten by p = h*gate) and gate. fp32, 256 MB each.
__device__ float g_u[(size_t)Mrows * HH];
__device__ float g_g[(size_t)Mrows * HH];

// ---------------------------------------------------------------------------
// Tile geometry: CTA 128x128, BK=32 bf16. 8 warps = 4(m) x 2(n), warp 32x64.
// smem rows padded to 40 halves (80B) for conflict-free ldmatrix.
// Stage holds A_hi, A_lo, B_hi, B_lo tiles; two stages double-buffered.
// ---------------------------------------------------------------------------
constexpr int BM = 128, BN = 128, BK = 32;
constexpr int ROW_HALFS   = 40;                 // 32 data + 8 pad
constexpr int TILE_HALFS  = BM * ROW_HALFS;     // 5120 halves / tile
constexpr int STAGE_HALFS = 4 * TILE_HALFS;     // Ah, Al, Bh, Bl
constexpr int SMEM_BYTES  = 2 * STAGE_HALFS * 2;  // 81920 B

__device__ __forceinline__ uint32_t smem_u32(const void* p) {
  uint32_t a;
  asm("{ .reg .u64 t; cvta.to.shared.u64 t, %1; cvt.u32.u64 %0, t; }"
      : "=r"(a) : "l"(p));
  return a;
}

__device__ __forceinline__ void ldsm4(uint32_t& r0, uint32_t& r1, uint32_t& r2,
                                      uint32_t& r3, uint32_t addr) {
  asm volatile("ldmatrix.sync.aligned.m8n8.x4.shared.b16 {%0,%1,%2,%3}, [%4];"
               : "=r"(r0), "=r"(r1), "=r"(r2), "=r"(r3) : "r"(addr));
}

__device__ __forceinline__ void mma16816(float* c, const uint32_t* a,
                                         uint32_t b0, uint32_t b1) {
  asm volatile(
      "mma.sync.aligned.m16n8k16.row.col.f32.bf16.bf16.f32 "
      "{%0,%1,%2,%3}, {%4,%5,%6,%7}, {%8,%9}, {%0,%1,%2,%3};"
      : "+f"(c[0]), "+f"(c[1]), "+f"(c[2]), "+f"(c[3])
      : "r"(a[0]), "r"(a[1]), "r"(a[2]), "r"(a[3]), "r"(b0), "r"(b1));
}

// Split (x,y) into packed bf16 hi pair and residual lo pair.
__device__ __forceinline__ void split2(float x, float y, uint32_t& h, uint32_t& l) {
  __nv_bfloat16 hx = __float2bfloat16_rn(x);
  __nv_bfloat16 hy = __float2bfloat16_rn(y);
  __nv_bfloat162 hp{hx, hy};
  h = *reinterpret_cast<uint32_t*>(&hp);
  __nv_bfloat162 lp = __floats2bfloat162_rn(x - __bfloat162float(hx),
                                            y - __bfloat162float(hy));
  l = *reinterpret_cast<uint32_t*>(&lp);
}

// ---------------------------------------------------------------------------
// C[m,n] = sum_k A[m,k]*Bw[n,k] + bias[n]; ACT: 0 none, 1 sigmoid.
// M,N multiples of 128; K multiple of 32.
// ---------------------------------------------------------------------------
template <int ACT>
__global__ __launch_bounds__(256, 1) void gemm_hmma(
    const float* __restrict__ A, const float* __restrict__ Bw,
    const float* __restrict__ bias, float* __restrict__ C, int N, int K) {
  extern __shared__ __nv_bfloat16 sm[];
  const uint32_t smb = smem_u32(sm);

  const int tid  = threadIdx.x;
  const int wid  = tid >> 5;
  const int lane = tid & 31;
  const int wm   = wid >> 1;   // 0..3
  const int wn   = wid & 1;    // 0..1
  const int m0   = blockIdx.y * BM;
  const int n0   = blockIdx.x * BN;

  float acc[2][8][4];
#pragma unroll
  for (int i = 0; i < 2; i++)
#pragma unroll
    for (int j = 0; j < 8; j++)
#pragma unroll
      for (int q = 0; q < 4; q++) acc[i][j][q] = 0.f;

  const float* Abase = A + (size_t)m0 * K;
  const float* Bbase = Bw + (size_t)n0 * K;

  // per-thread load slots: idx = tid + it*256; row = idx>>3 (0..127), q = idx&7
  const int lrow = tid >> 3;
  const int lq   = tid & 7;

  float4 ra[4], rb[4];

  // ---- load chunk 0 ----
#pragma unroll
  for (int it = 0; it < 4; it++) {
    int row = lrow + it * 32;
    ra[it] = *reinterpret_cast<const float4*>(Abase + (size_t)row * K + lq * 4);
    rb[it] = *reinterpret_cast<const float4*>(Bbase + (size_t)row * K + lq * 4);
  }
  // ---- store chunk 0 into stage 0 ----
#pragma unroll
  for (int it = 0; it < 4; it++) {
    int row = lrow + it * 32;
    int off = row * ROW_HALFS + lq * 4;
    uint32_t h0, l0, h1, l1;
    split2(ra[it].x, ra[it].y, h0, l0);
    split2(ra[it].z, ra[it].w, h1, l1);
    *reinterpret_cast<uint2*>(sm + off)              = make_uint2(h0, h1);
    *reinterpret_cast<uint2*>(sm + TILE_HALFS + off) = make_uint2(l0, l1);
    split2(rb[it].x, rb[it].y, h0, l0);
    split2(rb[it].z, rb[it].w, h1, l1);
    *reinterpret_cast<uint2*>(sm + 2 * TILE_HALFS + off) = make_uint2(h0, h1);
    *reinterpret_cast<uint2*>(sm + 3 * TILE_HALFS + off) = make_uint2(l0, l1);
  }
  __syncthreads();

  const int NC = K / BK;
  const int lr  = lane & 15;
  const int lc8 = lane >> 4;  // 0/1

  for (int c = 0; c < NC; c++) {
    const int s = c & 1;

    // Issue global loads for next chunk (latency hidden under compute).
    if (c + 1 < NC) {
      const float* Ap = Abase + (size_t)(c + 1) * BK;
      const float* Bp = Bbase + (size_t)(c + 1) * BK;
#pragma unroll
      for (int it = 0; it < 4; it++) {
        int row = lrow + it * 32;
        ra[it] = *reinterpret_cast<const float4*>(Ap + (size_t)row * K + lq * 4);
        rb[it] = *reinterpret_cast<const float4*>(Bp + (size_t)row * K + lq * 4);
      }
    }

    // ---- compute chunk c from stage s ----
    const uint32_t sA = smb + (uint32_t)(s * STAGE_HALFS) * 2;
    const uint32_t sB = sA + (uint32_t)(2 * TILE_HALFS) * 2;
#pragma unroll
    for (int ks = 0; ks < 2; ks++) {
      const uint32_t kbyte = (uint32_t)(ks * 16 + lc8 * 8) * 2;
      uint32_t a_hi[2][4], a_lo[2][4];
#pragma unroll
      for (int i = 0; i < 2; i++) {
        uint32_t ad = sA + (uint32_t)((wm * 32 + i * 16 + lr) * ROW_HALFS) * 2 + kbyte;
        ldsm4(a_hi[i][0], a_hi[i][1], a_hi[i][2], a_hi[i][3], ad);
        ldsm4(a_lo[i][0], a_lo[i][1], a_lo[i][2], a_lo[i][3],
              ad + (uint32_t)TILE_HALFS * 2);
      }
#pragma unroll
      for (int j = 0; j < 4; j++) {
        uint32_t bd = sB + (uint32_t)((wn * 64 + j * 16 + lr) * ROW_HALFS) * 2 + kbyte;
        uint32_t bh[4], bl[4];
        ldsm4(bh[0], bh[1], bh[2], bh[3], bd);
        ldsm4(bl[0], bl[1], bl[2], bl[3], bd + (uint32_t)TILE_HALFS * 2);
#pragma unroll
        for (int i = 0; i < 2; i++) {
          mma16816(acc[i][2 * j + 0], a_hi[i], bh[0], bh[2]);
          mma16816(acc[i][2 * j + 1], a_hi[i], bh[1], bh[3]);
          mma16816(acc[i][2 * j + 0], a_hi[i], bl[0], bl[2]);
          mma16816(acc[i][2 * j + 1], a_hi[i], bl[1], bl[3]);
          mma16816(acc[i][2 * j + 0], a_lo[i], bh[0], bh[2]);
          mma16816(acc[i][2 * j + 1], a_lo[i], bh[1], bh[3]);
        }
      }
    }

    // ---- convert + store next chunk into other stage ----
    if (c + 1 < NC) {
      __nv_bfloat16* dst = sm + (s ^ 1) * STAGE_HALFS;
#pragma unroll
      for (int it = 0; it < 4; it++) {
        int row = lrow + it * 32;
        int off = row * ROW_HALFS + lq * 4;
        uint32_t h0, l0, h1, l1;
        split2(ra[it].x, ra[it].y, h0, l0);
        split2(ra[it].z, ra[it].w, h1, l1);
        *reinterpret_cast<uint2*>(dst + off)              = make_uint2(h0, h1);
        *reinterpret_cast<uint2*>(dst + TILE_HALFS + off) = make_uint2(l0, l1);
        split2(rb[it].x, rb[it].y, h0, l0);
        split2(rb[it].z, rb[it].w, h1, l1);
        *reinterpret_cast<uint2*>(dst + 2 * TILE_HALFS + off) = make_uint2(h0, h1);
        *reinterpret_cast<uint2*>(dst + 3 * TILE_HALFS + off) = make_uint2(l0, l1);
      }
    }
    __syncthreads();
  }

  // ---- epilogue: bias + optional sigmoid, write C ----
#pragma unroll
  for (int i = 0; i < 2; i++) {
    int r0 = m0 + wm * 32 + i * 16 + (lane >> 2);
#pragma unroll
    for (int j = 0; j < 8; j++) {
      int col = n0 + wn * 64 + j * 8 + (lane & 3) * 2;
      float b0 = bias[col], b1 = bias[col + 1];
      float v0 = acc[i][j][0] + b0;
      float v1 = acc[i][j][1] + b1;
      float v2 = acc[i][j][2] + b0;
      float v3 = acc[i][j][3] + b1;
      if (ACT == 1) {
        v0 = 1.f / (1.f + expf(-v0));
        v1 = 1.f / (1.f + expf(-v1));
        v2 = 1.f / (1.f + expf(-v2));
        v3 = 1.f / (1.f + expf(-v3));
      }
      *reinterpret_cast<float2*>(&C[(size_t)r0 * N + col])       = make_float2(v0, v1);
      *reinterpret_cast<float2*>(&C[(size_t)(r0 + 8) * N + col]) = make_float2(v2, v3);
    }
  }
}

// ---------------------------------------------------------------------------
// Diagonal scan h_t = a*h_{t-1} + u_t, p_t = h_t*gate_t in place over u.
// ---------------------------------------------------------------------------
__global__ __launch_bounds__(256) void scan_gate_kernel(
    const float* __restrict__ log_a) {
  int idx = blockIdx.x * blockDim.x + threadIdx.x;
  int b = idx / HH;
  int h = idx % HH;
  float a = 1.f / (1.f + expf(-log_a[h]));
  float hs = 0.f;

  float* up = g_u + (size_t)b * Tt * HH + h;
  const float* gp = g_g + (size_t)b * Tt * HH + h;

  for (int t0 = 0; t0 < Tt; t0 += 16) {
    float uu[16], gg[16];
#pragma unroll
    for (int i = 0; i < 16; i++) {
      uu[i] = up[(size_t)(t0 + i) * HH];
      gg[i] = gp[(size_t)(t0 + i) * HH];
    }
#pragma unroll
    for (int i = 0; i < 16; i++) {
      hs = fmaf(a, hs, uu[i]);
      up[(size_t)(t0 + i) * HH] = hs * gg[i];
    }
  }
}

// ---------------------------------------------------------------------------
extern "C" void kernel_launch(void* const* d_in, const int* in_sizes, int n_in,
                              void* d_out, int out_size) {
  const float* x     = (const float*)d_in[0];
  const float* Wi    = (const float*)d_in[1];
  const float* bi    = (const float*)d_in[2];
  const float* Wg    = (const float*)d_in[3];
  const float* bg    = (const float*)d_in[4];
  const float* Wo    = (const float*)d_in[5];
  const float* bo    = (const float*)d_in[6];
  const float* log_a = (const float*)d_in[7];
  float* y = (float*)d_out;

  float* u_ptr = nullptr;
  float* g_ptr = nullptr;
  cudaGetSymbolAddress((void**)&u_ptr, g_u);
  cudaGetSymbolAddress((void**)&g_ptr, g_g);

  cudaFuncSetAttribute(gemm_hmma<0>, cudaFuncAttributeMaxDynamicSharedMemorySize,
                       SMEM_BYTES);
  cudaFuncSetAttribute(gemm_hmma<1>, cudaFuncAttributeMaxDynamicSharedMemorySize,
                       SMEM_BYTES);

  dim3 blk(256);
  gemm_hmma<0><<<dim3(HH / 128, Mrows / 128), blk, SMEM_BYTES>>>(x, Wi, bi, u_ptr, HH, DIN);
  gemm_hmma<1><<<dim3(HH / 128, Mrows / 128), blk, SMEM_BYTES>>>(x, Wg, bg, g_ptr, HH, DIN);

  scan_gate_kernel<<<(Bb * HH) / 256, 256>>>(log_a);

  gemm_hmma<0><<<dim3(DIN / 128, Mrows / 128), blk, SMEM_BYTES>>>(u_ptr, Wo, bo, y, DIN, HH);
}

// round 5
// speedup vs baseline: 2.0231x; 1.1244x over previous
#include <cuda_runtime.h>
#include <cuda_bf16.h>
#include <math.h>
#include <stdint.h>

// Problem constants
constexpr int Bb   = 8;
constexpr int Tt   = 4096;
constexpr int DIN  = 1024;
constexpr int HH   = 2048;
constexpr int Mrows = Bb * Tt;  // 32768

// fp32 scratch
__device__ float g_u[(size_t)Mrows * HH];
__device__ float g_g[(size_t)Mrows * HH];
// bf16 hi/lo split operands
__device__ __nv_bfloat16 g_xh[(size_t)Mrows * DIN];
__device__ __nv_bfloat16 g_xl[(size_t)Mrows * DIN];
__device__ __nv_bfloat16 g_ph[(size_t)Mrows * HH];
__device__ __nv_bfloat16 g_pl[(size_t)Mrows * HH];
__device__ __nv_bfloat16 g_wih[(size_t)HH * DIN];
__device__ __nv_bfloat16 g_wil[(size_t)HH * DIN];
__device__ __nv_bfloat16 g_wgh[(size_t)HH * DIN];
__device__ __nv_bfloat16 g_wgl[(size_t)HH * DIN];
__device__ __nv_bfloat16 g_woh[(size_t)DIN * HH];
__device__ __nv_bfloat16 g_wol[(size_t)DIN * HH];

// ---------------------------------------------------------------------------
constexpr int BM = 128, BN = 128, BK = 32;
constexpr int ROW_HALFS  = 40;                   // 32 data + 8 pad
constexpr int ROW_BYTES  = 80;
constexpr int TILE_BYTES = BM * ROW_BYTES;       // 10240
constexpr int STAGE_BYTES = 4 * TILE_BYTES;      // Ah, Al, Bh, Bl = 40960
constexpr int NSTAGES    = 4;
constexpr int SMEM_BYTES = NSTAGES * STAGE_BYTES;  // 163840

__device__ __forceinline__ uint32_t smem_u32(const void* p) {
  uint32_t a;
  asm("{ .reg .u64 t; cvta.to.shared.u64 t, %1; cvt.u32.u64 %0, t; }"
      : "=r"(a) : "l"(p));
  return a;
}
__device__ __forceinline__ void cp16(uint32_t dst, const void* src) {
  asm volatile("cp.async.cg.shared.global [%0], [%1], 16;"
               :: "r"(dst), "l"(src) : "memory");
}
__device__ __forceinline__ void cp_commit() {
  asm volatile("cp.async.commit_group;" ::: "memory");
}
template <int N>
__device__ __forceinline__ void cp_wait() {
  asm volatile("cp.async.wait_group %0;" :: "n"(N) : "memory");
}
__device__ __forceinline__ void ldsm4(uint32_t* r, uint32_t addr) {
  asm volatile("ldmatrix.sync.aligned.m8n8.x4.shared.b16 {%0,%1,%2,%3}, [%4];"
               : "=r"(r[0]), "=r"(r[1]), "=r"(r[2]), "=r"(r[3]) : "r"(addr));
}
__device__ __forceinline__ void mma16816(float* c, const uint32_t* a,
                                         uint32_t b0, uint32_t b1) {
  asm volatile(
      "mma.sync.aligned.m16n8k16.row.col.f32.bf16.bf16.f32 "
      "{%0,%1,%2,%3}, {%4,%5,%6,%7}, {%8,%9}, {%0,%1,%2,%3};"
      : "+f"(c[0]), "+f"(c[1]), "+f"(c[2]), "+f"(c[3])
      : "r"(a[0]), "r"(a[1]), "r"(a[2]), "r"(a[3]), "r"(b0), "r"(b1));
}
__device__ __forceinline__ void split2(float x, float y, uint32_t& h, uint32_t& l) {
  __nv_bfloat16 hx = __float2bfloat16_rn(x);
  __nv_bfloat16 hy = __float2bfloat16_rn(y);
  __nv_bfloat162 hp{hx, hy};
  h = *reinterpret_cast<uint32_t*>(&hp);
  __nv_bfloat162 lp = __floats2bfloat162_rn(x - __bfloat162float(hx),
                                            y - __bfloat162float(hy));
  l = *reinterpret_cast<uint32_t*>(&lp);
}

// ---------------------------------------------------------------------------
// Pure-bf16 split GEMM: C[m,n] = sum_k (Ah+Al)[m,k]*(Bh+Bl)[n,k] + bias[n]
// (lo*lo dropped). cp.async 4-stage pipeline, 8 warps = 4m x 2n, warp 32x64.
// ---------------------------------------------------------------------------
template <int ACT>
__global__ __launch_bounds__(256, 1) void gemm_bf16s(
    const __nv_bfloat16* __restrict__ Ah, const __nv_bfloat16* __restrict__ Al,
    const __nv_bfloat16* __restrict__ Bh, const __nv_bfloat16* __restrict__ Bl,
    const float* __restrict__ bias, float* __restrict__ C, int N, int K) {
  extern __shared__ char sm[];
  const uint32_t smb = smem_u32(sm);

  const int tid  = threadIdx.x;
  const int wid  = tid >> 5;
  const int lane = tid & 31;
  const int wm   = wid >> 1;
  const int wn   = wid & 1;
  const int m0   = blockIdx.y * BM;
  const int n0   = blockIdx.x * BN;

  // load mapping: thread handles rows {row0, row0+64}, 16B chunk c16, all 4 tiles
  const int row0 = tid >> 2;
  const int c16  = tid & 3;
  const __nv_bfloat16* src[4];
  src[0] = Ah + (size_t)(m0 + row0) * K + c16 * 8;
  src[1] = Al + (size_t)(m0 + row0) * K + c16 * 8;
  src[2] = Bh + (size_t)(n0 + row0) * K + c16 * 8;
  src[3] = Bl + (size_t)(n0 + row0) * K + c16 * 8;
  const size_t rstep = (size_t)64 * K;
  const uint32_t dbase = (uint32_t)(row0 * ROW_BYTES + c16 * 16);

  float acc[2][8][4];
#pragma unroll
  for (int i = 0; i < 2; i++)
#pragma unroll
    for (int j = 0; j < 8; j++)
#pragma unroll
      for (int q = 0; q < 4; q++) acc[i][j][q] = 0.f;

  const int NC = K / BK;

  auto issue = [&](int s, int c) {
    const uint32_t d = smb + (uint32_t)s * STAGE_BYTES + dbase;
#pragma unroll
    for (int t = 0; t < 4; t++) {
      const __nv_bfloat16* sp = src[t] + c * BK;
      cp16(d + t * TILE_BYTES, sp);
      cp16(d + t * TILE_BYTES + 64 * ROW_BYTES, sp + rstep);
    }
    cp_commit();
  };

  issue(0, 0); issue(1, 1); issue(2, 2);

  const int lr  = lane & 15;
  const int lc8 = lane >> 4;

  for (int c = 0; c < NC; c++) {
    cp_wait<2>();
    __syncthreads();
    if (c + 3 < NC) issue((c + 3) & 3, c + 3);

    const uint32_t sA = smb + (uint32_t)(c & 3) * STAGE_BYTES;
    const uint32_t sB = sA + 2 * TILE_BYTES;
#pragma unroll
    for (int ks = 0; ks < 2; ks++) {
      const uint32_t kbyte = (uint32_t)(ks * 32 + lc8 * 16);
      uint32_t ah[2][4], al[2][4], bh[4][4], bl[4][4];
#pragma unroll
      for (int i = 0; i < 2; i++) {
        uint32_t ad = sA + (uint32_t)((wm * 32 + i * 16 + lr) * ROW_BYTES) + kbyte;
        ldsm4(ah[i], ad);
        ldsm4(al[i], ad + TILE_BYTES);
      }
#pragma unroll
      for (int j = 0; j < 4; j++) {
        uint32_t bd = sB + (uint32_t)((wn * 64 + j * 16 + lr) * ROW_BYTES) + kbyte;
        ldsm4(bh[j], bd);
        ldsm4(bl[j], bd + TILE_BYTES);
      }
      // pass 1: Ah*Bh — 16 MMAs, all-distinct accumulators
#pragma unroll
      for (int j = 0; j < 4; j++)
#pragma unroll
        for (int i = 0; i < 2; i++) {
          mma16816(acc[i][2 * j + 0], ah[i], bh[j][0], bh[j][2]);
          mma16816(acc[i][2 * j + 1], ah[i], bh[j][1], bh[j][3]);
        }
      // pass 2: Ah*Bl
#pragma unroll
      for (int j = 0; j < 4; j++)
#pragma unroll
        for (int i = 0; i < 2; i++) {
          mma16816(acc[i][2 * j + 0], ah[i], bl[j][0], bl[j][2]);
          mma16816(acc[i][2 * j + 1], ah[i], bl[j][1], bl[j][3]);
        }
      // pass 3: Al*Bh
#pragma unroll
      for (int j = 0; j < 4; j++)
#pragma unroll
        for (int i = 0; i < 2; i++) {
          mma16816(acc[i][2 * j + 0], al[i], bh[j][0], bh[j][2]);
          mma16816(acc[i][2 * j + 1], al[i], bh[j][1], bh[j][3]);
        }
    }
    __syncthreads();
  }

  // epilogue
#pragma unroll
  for (int i = 0; i < 2; i++) {
    int r0 = m0 + wm * 32 + i * 16 + (lane >> 2);
#pragma unroll
    for (int j = 0; j < 8; j++) {
      int col = n0 + wn * 64 + j * 8 + (lane & 3) * 2;
      float b0 = bias[col], b1 = bias[col + 1];
      float v0 = acc[i][j][0] + b0;
      float v1 = acc[i][j][1] + b1;
      float v2 = acc[i][j][2] + b0;
      float v3 = acc[i][j][3] + b1;
      if (ACT == 1) {
        v0 = 1.f / (1.f + expf(-v0));
        v1 = 1.f / (1.f + expf(-v1));
        v2 = 1.f / (1.f + expf(-v2));
        v3 = 1.f / (1.f + expf(-v3));
      }
      *reinterpret_cast<float2*>(&C[(size_t)r0 * N + col])       = make_float2(v0, v1);
      *reinterpret_cast<float2*>(&C[(size_t)(r0 + 8) * N + col]) = make_float2(v2, v3);
    }
  }
}

// ---------------------------------------------------------------------------
// Elementwise fp32 -> bf16 hi/lo split (float4 per thread).
// ---------------------------------------------------------------------------
__global__ __launch_bounds__(256) void split_kernel(
    const float* __restrict__ src, __nv_bfloat16* __restrict__ hi,
    __nv_bfloat16* __restrict__ lo, int n4) {
  int i = blockIdx.x * blockDim.x + threadIdx.x;
  if (i >= n4) return;
  float4 v = reinterpret_cast<const float4*>(src)[i];
  uint32_t h0, l0, h1, l1;
  split2(v.x, v.y, h0, l0);
  split2(v.z, v.w, h1, l1);
  reinterpret_cast<uint2*>(hi)[i] = make_uint2(h0, h1);
  reinterpret_cast<uint2*>(lo)[i] = make_uint2(l0, l1);
}

// ---------------------------------------------------------------------------
// Scan: h_t = a*h_{t-1} + u_t; p_t = h_t*g_t written as bf16 hi/lo.
// ---------------------------------------------------------------------------
__global__ __launch_bounds__(256) void scan_gate_kernel(
    const float* __restrict__ log_a) {
  int idx = blockIdx.x * blockDim.x + threadIdx.x;
  int b = idx / HH;
  int h = idx % HH;
  float a = 1.f / (1.f + expf(-log_a[h]));
  float hs = 0.f;

  const float* up = g_u + (size_t)b * Tt * HH + h;
  const float* gp = g_g + (size_t)b * Tt * HH + h;
  __nv_bfloat16* ph = g_ph + (size_t)b * Tt * HH + h;
  __nv_bfloat16* pl = g_pl + (size_t)b * Tt * HH + h;

  for (int t0 = 0; t0 < Tt; t0 += 16) {
    float uu[16], gg[16];
#pragma unroll
    for (int i = 0; i < 16; i++) {
      uu[i] = up[(size_t)(t0 + i) * HH];
      gg[i] = gp[(size_t)(t0 + i) * HH];
    }
#pragma unroll
    for (int i = 0; i < 16; i++) {
      hs = fmaf(a, hs, uu[i]);
      float p = hs * gg[i];
      __nv_bfloat16 hb = __float2bfloat16_rn(p);
      ph[(size_t)(t0 + i) * HH] = hb;
      pl[(size_t)(t0 + i) * HH] = __float2bfloat16_rn(p - __bfloat162float(hb));
    }
  }
}

// ---------------------------------------------------------------------------
extern "C" void kernel_launch(void* const* d_in, const int* in_sizes, int n_in,
                              void* d_out, int out_size) {
  const float* x     = (const float*)d_in[0];
  const float* Wi    = (const float*)d_in[1];
  const float* bi    = (const float*)d_in[2];
  const float* Wg    = (const float*)d_in[3];
  const float* bg    = (const float*)d_in[4];
  const float* Wo    = (const float*)d_in[5];
  const float* bo    = (const float*)d_in[6];
  const float* log_a = (const float*)d_in[7];
  float* y = (float*)d_out;

  float *u_p, *g_p;
  __nv_bfloat16 *xh, *xl, *ph, *pl, *wih, *wil, *wgh, *wgl, *woh, *wol;
  cudaGetSymbolAddress((void**)&u_p, g_u);
  cudaGetSymbolAddress((void**)&g_p, g_g);
  cudaGetSymbolAddress((void**)&xh, g_xh);
  cudaGetSymbolAddress((void**)&xl, g_xl);
  cudaGetSymbolAddress((void**)&ph, g_ph);
  cudaGetSymbolAddress((void**)&pl, g_pl);
  cudaGetSymbolAddress((void**)&wih, g_wih);
  cudaGetSymbolAddress((void**)&wil, g_wil);
  cudaGetSymbolAddress((void**)&wgh, g_wgh);
  cudaGetSymbolAddress((void**)&wgl, g_wgl);
  cudaGetSymbolAddress((void**)&woh, g_woh);
  cudaGetSymbolAddress((void**)&wol, g_wol);

  cudaFuncSetAttribute(gemm_bf16s<0>, cudaFuncAttributeMaxDynamicSharedMemorySize,
                       SMEM_BYTES);
  cudaFuncSetAttribute(gemm_bf16s<1>, cudaFuncAttributeMaxDynamicSharedMemorySize,
                       SMEM_BYTES);

  // Pre-split inputs
  int n4x = Mrows * DIN / 4;      // 8M float4
  int n4w = HH * DIN / 4;         // 512K float4
  split_kernel<<<n4x / 256, 256>>>(x, xh, xl, n4x);
  split_kernel<<<n4w / 256, 256>>>(Wi, wih, wil, n4w);
  split_kernel<<<n4w / 256, 256>>>(Wg, wgh, wgl, n4w);
  split_kernel<<<n4w / 256, 256>>>(Wo, woh, wol, n4w);

  dim3 blk(256);
  gemm_bf16s<0><<<dim3(HH / BN, Mrows / BM), blk, SMEM_BYTES>>>(
      xh, xl, wih, wil, bi, u_p, HH, DIN);
  gemm_bf16s<1><<<dim3(HH / BN, Mrows / BM), blk, SMEM_BYTES>>>(
      xh, xl, wgh, wgl, bg, g_p, HH, DIN);

  scan_gate_kernel<<<(Bb * HH) / 256, 256>>>(log_a);

  gemm_bf16s<0><<<dim3(DIN / BN, Mrows / BM), blk, SMEM_BYTES>>>(
      ph, pl, woh, wol, bo, y, DIN, HH);
}

// round 6
// speedup vs baseline: 2.1433x; 1.0594x over previous
#include <cuda_runtime.h>
#include <cuda_bf16.h>
#include <math.h>
#include <stdint.h>

// Problem constants
constexpr int Bb   = 8;
constexpr int Tt   = 4096;
constexpr int DIN  = 1024;
constexpr int HH   = 2048;
constexpr int Mrows = Bb * Tt;  // 32768

// fp32 scratch
__device__ float g_u[(size_t)Mrows * HH];
__device__ float g_g[(size_t)Mrows * HH];
// bf16 hi/lo split operands
__device__ __nv_bfloat16 g_xh[(size_t)Mrows * DIN];
__device__ __nv_bfloat16 g_xl[(size_t)Mrows * DIN];
__device__ __nv_bfloat16 g_ph[(size_t)Mrows * HH];
__device__ __nv_bfloat16 g_pl[(size_t)Mrows * HH];
__device__ __nv_bfloat16 g_wih[(size_t)HH * DIN];
__device__ __nv_bfloat16 g_wil[(size_t)HH * DIN];
__device__ __nv_bfloat16 g_wgh[(size_t)HH * DIN];
__device__ __nv_bfloat16 g_wgl[(size_t)HH * DIN];
__device__ __nv_bfloat16 g_woh[(size_t)DIN * HH];
__device__ __nv_bfloat16 g_wol[(size_t)DIN * HH];

// ---------------------------------------------------------------------------
// CTA tile 256(M) x 128(N), BK=32. 8 warps = 4m x 2n, warp tile 64x64.
// smem rows: 32 bf16 data padded to 80 bytes (conflict-free ldmatrix).
// Stage = Ah(256x32) Al Bh(128x32) Bl. 3 stages, cp.async pipeline.
// ---------------------------------------------------------------------------
constexpr int BM = 256, BN = 128, BK = 32;
constexpr int ROW_BYTES = 80;
constexpr int AT_BYTES  = BM * ROW_BYTES;   // 20480 per A tile
constexpr int BT_BYTES  = BN * ROW_BYTES;   // 10240 per B tile
constexpr int OFF_AH = 0;
constexpr int OFF_AL = AT_BYTES;            // 20480
constexpr int OFF_BH = 2 * AT_BYTES;        // 40960
constexpr int OFF_BL = 2 * AT_BYTES + BT_BYTES;  // 51200
constexpr int STAGE_BYTES = 2 * AT_BYTES + 2 * BT_BYTES;  // 61440
constexpr int NSTAGES = 3;
constexpr int SMEM_BYTES = NSTAGES * STAGE_BYTES;  // 184320

__device__ __forceinline__ uint32_t smem_u32(const void* p) {
  uint32_t a;
  asm("{ .reg .u64 t; cvta.to.shared.u64 t, %1; cvt.u32.u64 %0, t; }"
      : "=r"(a) : "l"(p));
  return a;
}
__device__ __forceinline__ void cp16(uint32_t dst, const void* src) {
  asm volatile("cp.async.cg.shared.global [%0], [%1], 16;"
               :: "r"(dst), "l"(src) : "memory");
}
__device__ __forceinline__ void cp_commit() {
  asm volatile("cp.async.commit_group;" ::: "memory");
}
template <int N>
__device__ __forceinline__ void cp_wait() {
  asm volatile("cp.async.wait_group %0;" :: "n"(N) : "memory");
}
__device__ __forceinline__ void ldsm4(uint32_t* r, uint32_t addr) {
  asm volatile("ldmatrix.sync.aligned.m8n8.x4.shared.b16 {%0,%1,%2,%3}, [%4];"
               : "=r"(r[0]), "=r"(r[1]), "=r"(r[2]), "=r"(r[3]) : "r"(addr));
}
__device__ __forceinline__ void mma16816(float* c, const uint32_t* a,
                                         uint32_t b0, uint32_t b1) {
  asm volatile(
      "mma.sync.aligned.m16n8k16.row.col.f32.bf16.bf16.f32 "
      "{%0,%1,%2,%3}, {%4,%5,%6,%7}, {%8,%9}, {%0,%1,%2,%3};"
      : "+f"(c[0]), "+f"(c[1]), "+f"(c[2]), "+f"(c[3])
      : "r"(a[0]), "r"(a[1]), "r"(a[2]), "r"(a[3]), "r"(b0), "r"(b1));
}
__device__ __forceinline__ void split2(float x, float y, uint32_t& h, uint32_t& l) {
  __nv_bfloat16 hx = __float2bfloat16_rn(x);
  __nv_bfloat16 hy = __float2bfloat16_rn(y);
  __nv_bfloat162 hp{hx, hy};
  h = *reinterpret_cast<uint32_t*>(&hp);
  __nv_bfloat162 lp = __floats2bfloat162_rn(x - __bfloat162float(hx),
                                            y - __bfloat162float(hy));
  l = *reinterpret_cast<uint32_t*>(&lp);
}

// ---------------------------------------------------------------------------
// Split-bf16 GEMM: C[m,n] = sum_k (Ah+Al)[m,k]*(Bh+Bl)[n,k] + bias[n],
// dropping Al*Bl. ACT: 0 none, 1 sigmoid. M mult of 256, N mult of 128,
// K mult of 32.
// ---------------------------------------------------------------------------
template <int ACT>
__global__ __launch_bounds__(256, 1) void gemm_bf16s(
    const __nv_bfloat16* __restrict__ Ah, const __nv_bfloat16* __restrict__ Al,
    const __nv_bfloat16* __restrict__ Bh, const __nv_bfloat16* __restrict__ Bl,
    const float* __restrict__ bias, float* __restrict__ C, int N, int K) {
  extern __shared__ char sm[];
  const uint32_t smb = smem_u32(sm);

  const int tid  = threadIdx.x;
  const int wid  = tid >> 5;
  const int lane = tid & 31;
  const int wm   = wid >> 1;   // 0..3 (64-row slice)
  const int wn   = wid & 1;    // 0..1 (64-col slice)
  const int m0   = blockIdx.y * BM;
  const int n0   = blockIdx.x * BN;

  // cp.async mapping: 256 threads; row0 = tid>>2 (0..63), c16 = tid&3.
  const int row0 = tid >> 2;
  const int c16  = tid & 3;
  const __nv_bfloat16* aH = Ah + (size_t)(m0 + row0) * K + c16 * 8;
  const __nv_bfloat16* aL = Al + (size_t)(m0 + row0) * K + c16 * 8;
  const __nv_bfloat16* bH = Bh + (size_t)(n0 + row0) * K + c16 * 8;
  const __nv_bfloat16* bL = Bl + (size_t)(n0 + row0) * K + c16 * 8;
  const size_t rstep = (size_t)64 * K;
  const uint32_t dOff = (uint32_t)(row0 * ROW_BYTES + c16 * 16);

  float acc[4][8][4];
#pragma unroll
  for (int i = 0; i < 4; i++)
#pragma unroll
    for (int j = 0; j < 8; j++)
#pragma unroll
      for (int q = 0; q < 4; q++) acc[i][j][q] = 0.f;

  const int NC = K / BK;

  auto issue = [&](int s, int c) {
    const uint32_t d = smb + (uint32_t)s * STAGE_BYTES + dOff;
    const size_t koff = (size_t)c * BK;
#pragma unroll
    for (int it = 0; it < 4; it++) {  // A: 256 rows, hi+lo
      cp16(d + OFF_AH + it * 64 * ROW_BYTES, aH + koff + it * rstep);
      cp16(d + OFF_AL + it * 64 * ROW_BYTES, aL + koff + it * rstep);
    }
#pragma unroll
    for (int it = 0; it < 2; it++) {  // B: 128 rows, hi+lo
      cp16(d + OFF_BH + it * 64 * ROW_BYTES, bH + koff + it * rstep);
      cp16(d + OFF_BL + it * 64 * ROW_BYTES, bL + koff + it * rstep);
    }
    cp_commit();
  };

  issue(0, 0); issue(1, 1); issue(2, 2);

  const int lr  = lane & 15;
  const int lc8 = lane >> 4;

  for (int c = 0; c < NC; c++) {
    cp_wait<2>();
    __syncthreads();

    const uint32_t sS = smb + (uint32_t)(c % 3) * STAGE_BYTES;
#pragma unroll
    for (int ks = 0; ks < 2; ks++) {
      const uint32_t kbyte = (uint32_t)(ks * 32 + lc8 * 16);
      uint32_t ah[4][4], al[4][4];
#pragma unroll
      for (int i = 0; i < 4; i++) {
        uint32_t ad = sS + (uint32_t)((wm * 64 + i * 16 + lr) * ROW_BYTES) + kbyte;
        ldsm4(ah[i], ad + OFF_AH);
        ldsm4(al[i], ad + (OFF_AL - OFF_AH));  // same as ad + OFF_AL since OFF_AH=0
      }
#pragma unroll
      for (int j = 0; j < 4; j++) {
        uint32_t bd = sS + (uint32_t)((wn * 64 + j * 16 + lr) * ROW_BYTES) + kbyte;
        uint32_t bh[4], bl[4];
        ldsm4(bh, bd + OFF_BH);
        ldsm4(bl, bd + OFF_BL);
        // pass 1: Ah*Bh
#pragma unroll
        for (int i = 0; i < 4; i++) {
          mma16816(acc[i][2 * j + 0], ah[i], bh[0], bh[2]);
          mma16816(acc[i][2 * j + 1], ah[i], bh[1], bh[3]);
        }
        // pass 2: Ah*Bl
#pragma unroll
        for (int i = 0; i < 4; i++) {
          mma16816(acc[i][2 * j + 0], ah[i], bl[0], bl[2]);
          mma16816(acc[i][2 * j + 1], ah[i], bl[1], bl[3]);
        }
        // pass 3: Al*Bh
#pragma unroll
        for (int i = 0; i < 4; i++) {
          mma16816(acc[i][2 * j + 0], al[i], bh[0], bh[2]);
          mma16816(acc[i][2 * j + 1], al[i], bh[1], bh[3]);
        }
      }
    }
    __syncthreads();
    if (c + 3 < NC) issue(c % 3, c + 3);
  }

  // Epilogue: warp writes its 64x64 block.
#pragma unroll
  for (int i = 0; i < 4; i++) {
    int r0 = m0 + wm * 64 + i * 16 + (lane >> 2);
#pragma unroll
    for (int j = 0; j < 8; j++) {
      int col = n0 + wn * 64 + j * 8 + (lane & 3) * 2;
      float b0 = bias[col], b1 = bias[col + 1];
      float v0 = acc[i][j][0] + b0;
      float v1 = acc[i][j][1] + b1;
      float v2 = acc[i][j][2] + b0;
      float v3 = acc[i][j][3] + b1;
      if (ACT == 1) {
        v0 = 1.f / (1.f + expf(-v0));
        v1 = 1.f / (1.f + expf(-v1));
        v2 = 1.f / (1.f + expf(-v2));
        v3 = 1.f / (1.f + expf(-v3));
      }
      *reinterpret_cast<float2*>(&C[(size_t)r0 * N + col])       = make_float2(v0, v1);
      *reinterpret_cast<float2*>(&C[(size_t)(r0 + 8) * N + col]) = make_float2(v2, v3);
    }
  }
}

// ---------------------------------------------------------------------------
// Elementwise fp32 -> bf16 hi/lo split (float4 per thread).
// ---------------------------------------------------------------------------
__global__ __launch_bounds__(256) void split_kernel(
    const float* __restrict__ src, __nv_bfloat16* __restrict__ hi,
    __nv_bfloat16* __restrict__ lo, int n4) {
  int i = blockIdx.x * blockDim.x + threadIdx.x;
  if (i >= n4) return;
  float4 v = reinterpret_cast<const float4*>(src)[i];
  uint32_t h0, l0, h1, l1;
  split2(v.x, v.y, h0, l0);
  split2(v.z, v.w, h1, l1);
  reinterpret_cast<uint2*>(hi)[i] = make_uint2(h0, h1);
  reinterpret_cast<uint2*>(lo)[i] = make_uint2(l0, l1);
}

// ---------------------------------------------------------------------------
// Scan: h_t = a*h_{t-1} + u_t; p_t = h_t*g_t written as bf16 hi/lo.
// ---------------------------------------------------------------------------
__global__ __launch_bounds__(256) void scan_gate_kernel(
    const float* __restrict__ log_a) {
  int idx = blockIdx.x * blockDim.x + threadIdx.x;
  int b = idx / HH;
  int h = idx % HH;
  float a = 1.f / (1.f + expf(-log_a[h]));
  float hs = 0.f;

  const float* up = g_u + (size_t)b * Tt * HH + h;
  const float* gp = g_g + (size_t)b * Tt * HH + h;
  __nv_bfloat16* ph = g_ph + (size_t)b * Tt * HH + h;
  __nv_bfloat16* pl = g_pl + (size_t)b * Tt * HH + h;

  for (int t0 = 0; t0 < Tt; t0 += 16) {
    float uu[16], gg[16];
#pragma unroll
    for (int i = 0; i < 16; i++) {
      uu[i] = up[(size_t)(t0 + i) * HH];
      gg[i] = gp[(size_t)(t0 + i) * HH];
    }
#pragma unroll
    for (int i = 0; i < 16; i++) {
      hs = fmaf(a, hs, uu[i]);
      float p = hs * gg[i];
      __nv_bfloat16 hb = __float2bfloat16_rn(p);
      ph[(size_t)(t0 + i) * HH] = hb;
      pl[(size_t)(t0 + i) * HH] = __float2bfloat16_rn(p - __bfloat162float(hb));
    }
  }
}

// ---------------------------------------------------------------------------
extern "C" void kernel_launch(void* const* d_in, const int* in_sizes, int n_in,
                              void* d_out, int out_size) {
  const float* x     = (const float*)d_in[0];
  const float* Wi    = (const float*)d_in[1];
  const float* bi    = (const float*)d_in[2];
  const float* Wg    = (const float*)d_in[3];
  const float* bg    = (const float*)d_in[4];
  const float* Wo    = (const float*)d_in[5];
  const float* bo    = (const float*)d_in[6];
  const float* log_a = (const float*)d_in[7];
  float* y = (float*)d_out;

  float *u_p, *g_p;
  __nv_bfloat16 *xh, *xl, *ph, *pl, *wih, *wil, *wgh, *wgl, *woh, *wol;
  cudaGetSymbolAddress((void**)&u_p, g_u);
  cudaGetSymbolAddress((void**)&g_p, g_g);
  cudaGetSymbolAddress((void**)&xh, g_xh);
  cudaGetSymbolAddress((void**)&xl, g_xl);
  cudaGetSymbolAddress((void**)&ph, g_ph);
  cudaGetSymbolAddress((void**)&pl, g_pl);
  cudaGetSymbolAddress((void**)&wih, g_wih);
  cudaGetSymbolAddress((void**)&wil, g_wil);
  cudaGetSymbolAddress((void**)&wgh, g_wgh);
  cudaGetSymbolAddress((void**)&wgl, g_wgl);
  cudaGetSymbolAddress((void**)&woh, g_woh);
  cudaGetSymbolAddress((void**)&wol, g_wol);

  cudaFuncSetAttribute(gemm_bf16s<0>, cudaFuncAttributeMaxDynamicSharedMemorySize,
                       SMEM_BYTES);
  cudaFuncSetAttribute(gemm_bf16s<1>, cudaFuncAttributeMaxDynamicSharedMemorySize,
                       SMEM_BYTES);

  // Pre-split inputs
  int n4x = Mrows * DIN / 4;
  int n4w = HH * DIN / 4;
  split_kernel<<<n4x / 256, 256>>>(x, xh, xl, n4x);
  split_kernel<<<n4w / 256, 256>>>(Wi, wih, wil, n4w);
  split_kernel<<<n4w / 256, 256>>>(Wg, wgh, wgl, n4w);
  split_kernel<<<n4w / 256, 256>>>(Wo, woh, wol, n4w);

  dim3 blk(256);
  gemm_bf16s<0><<<dim3(HH / BN, Mrows / BM), blk, SMEM_BYTES>>>(
      xh, xl, wih, wil, bi, u_p, HH, DIN);
  gemm_bf16s<1><<<dim3(HH / BN, Mrows / BM), blk, SMEM_BYTES>>>(
      xh, xl, wgh, wgl, bg, g_p, HH, DIN);

  scan_gate_kernel<<<(Bb * HH) / 256, 256>>>(log_a);

  gemm_bf16s<0><<<dim3(DIN / BN, Mrows / BM), blk, SMEM_BYTES>>>(
      ph, pl, woh, wol, bo, y, DIN, HH);
}

// round 7
// speedup vs baseline: 2.5841x; 1.2056x over previous
#include <cuda_runtime.h>
#include <cuda_bf16.h>
#include <math.h>
#include <stdint.h>

// Problem constants
constexpr int Bb   = 8;
constexpr int Tt   = 4096;
constexpr int DIN  = 1024;
constexpr int HH   = 2048;
constexpr int Mrows = Bb * Tt;  // 32768

// fp32 scratch
__device__ float g_u[(size_t)Mrows * HH];
__device__ float g_g[(size_t)Mrows * HH];
// bf16 hi/lo split operands
__device__ __nv_bfloat16 g_xh[(size_t)Mrows * DIN];
__device__ __nv_bfloat16 g_xl[(size_t)Mrows * DIN];
__device__ __nv_bfloat16 g_ph[(size_t)Mrows * HH];
__device__ __nv_bfloat16 g_pl[(size_t)Mrows * HH];
__device__ __nv_bfloat16 g_wih[(size_t)HH * DIN];
__device__ __nv_bfloat16 g_wil[(size_t)HH * DIN];
__device__ __nv_bfloat16 g_wgh[(size_t)HH * DIN];
__device__ __nv_bfloat16 g_wgl[(size_t)HH * DIN];
__device__ __nv_bfloat16 g_woh[(size_t)DIN * HH];
__device__ __nv_bfloat16 g_wol[(size_t)DIN * HH];

// ---------------------------------------------------------------------------
// CTA tile 256(M) x 128(N), BK=64 (128-byte bf16 rows, SW128 XOR swizzle,
// no padding). 8 warps = 4m x 2n, warp tile 64x64. 2-stage cp.async pipeline.
// ---------------------------------------------------------------------------
constexpr int BM = 256, BN = 128, BK = 64;
constexpr int AT_BYTES = BM * 128;          // 32768 per A tile (hi or lo)
constexpr int BT_BYTES = BN * 128;          // 16384 per B tile
constexpr int OFF_AH = 0;
constexpr int OFF_AL = AT_BYTES;            // 32768
constexpr int OFF_BH = 2 * AT_BYTES;        // 65536
constexpr int OFF_BL = 2 * AT_BYTES + BT_BYTES;  // 81920
constexpr int STAGE_BYTES = 2 * AT_BYTES + 2 * BT_BYTES;  // 98304
constexpr int SMEM_BYTES  = 2 * STAGE_BYTES;              // 196608

__device__ __forceinline__ uint32_t smem_u32(const void* p) {
  uint32_t a;
  asm("{ .reg .u64 t; cvta.to.shared.u64 t, %1; cvt.u32.u64 %0, t; }"
      : "=r"(a) : "l"(p));
  return a;
}
__device__ __forceinline__ void cp16(uint32_t dst, const void* src) {
  asm volatile("cp.async.cg.shared.global [%0], [%1], 16;"
               :: "r"(dst), "l"(src) : "memory");
}
__device__ __forceinline__ void cp_commit() {
  asm volatile("cp.async.commit_group;" ::: "memory");
}
template <int N>
__device__ __forceinline__ void cp_wait() {
  asm volatile("cp.async.wait_group %0;" :: "n"(N) : "memory");
}
__device__ __forceinline__ void ldsm4(uint32_t* r, uint32_t addr) {
  asm volatile("ldmatrix.sync.aligned.m8n8.x4.shared.b16 {%0,%1,%2,%3}, [%4];"
               : "=r"(r[0]), "=r"(r[1]), "=r"(r[2]), "=r"(r[3]) : "r"(addr));
}
__device__ __forceinline__ void mma16816(float* c, const uint32_t* a,
                                         uint32_t b0, uint32_t b1) {
  asm volatile(
      "mma.sync.aligned.m16n8k16.row.col.f32.bf16.bf16.f32 "
      "{%0,%1,%2,%3}, {%4,%5,%6,%7}, {%8,%9}, {%0,%1,%2,%3};"
      : "+f"(c[0]), "+f"(c[1]), "+f"(c[2]), "+f"(c[3])
      : "r"(a[0]), "r"(a[1]), "r"(a[2]), "r"(a[3]), "r"(b0), "r"(b1));
}
__device__ __forceinline__ void split2(float x, float y, uint32_t& h, uint32_t& l) {
  __nv_bfloat16 hx = __float2bfloat16_rn(x);
  __nv_bfloat16 hy = __float2bfloat16_rn(y);
  __nv_bfloat162 hp{hx, hy};
  h = *reinterpret_cast<uint32_t*>(&hp);
  __nv_bfloat162 lp = __floats2bfloat162_rn(x - __bfloat162float(hx),
                                            y - __bfloat162float(hy));
  l = *reinterpret_cast<uint32_t*>(&lp);
}

// ---------------------------------------------------------------------------
// Fused split-bf16 GEMM. CTAs with blockIdx.x < ntiles1 compute
//   C1 = A*B1^T + bias1 (no act); the rest compute C2 = sigmoid(A*B2^T+bias2).
// C[m,n] = sum_k (Ah+Al)(Bh+Bl) dropping Al*Bl. M mult 256, N mult 128, K mult 64.
// ---------------------------------------------------------------------------
__global__ __launch_bounds__(256, 1) void gemm_bf16s(
    const __nv_bfloat16* __restrict__ Ah, const __nv_bfloat16* __restrict__ Al,
    const __nv_bfloat16* __restrict__ B1h, const __nv_bfloat16* __restrict__ B1l,
    const float* __restrict__ bias1, float* __restrict__ C1,
    const __nv_bfloat16* __restrict__ B2h, const __nv_bfloat16* __restrict__ B2l,
    const float* __restrict__ bias2, float* __restrict__ C2,
    int ntiles1, int N, int K) {
  extern __shared__ char sm[];
  const uint32_t smb = smem_u32(sm);

  const int tid  = threadIdx.x;
  const int wid  = tid >> 5;
  const int lane = tid & 31;
  const int wm   = wid >> 1;
  const int wn   = wid & 1;

  const int bx = blockIdx.x;
  const bool second = (bx >= ntiles1);
  const __nv_bfloat16* Bh = second ? B2h : B1h;
  const __nv_bfloat16* Bl = second ? B2l : B1l;
  const float* bias = second ? bias2 : bias1;
  float* C = second ? C2 : C1;
  const int n0 = (second ? bx - ntiles1 : bx) * BN;
  const int m0 = blockIdx.y * BM;

  // cp.async mapping: row0 = tid>>3 (0..31), c16 = tid&7 (16B chunk in 128B row)
  const int row0 = tid >> 3;
  const int c16  = tid & 7;
  const uint32_t swc16 = (uint32_t)((c16 ^ (row0 & 7)) * 16);  // SW128
  const __nv_bfloat16* aHp = Ah + (size_t)(m0 + row0) * K + c16 * 8;
  const __nv_bfloat16* aLp = Al + (size_t)(m0 + row0) * K + c16 * 8;
  const __nv_bfloat16* bHp = Bh + (size_t)(n0 + row0) * K + c16 * 8;
  const __nv_bfloat16* bLp = Bl + (size_t)(n0 + row0) * K + c16 * 8;
  const size_t rstep = (size_t)32 * K;

  float acc[4][8][4];
#pragma unroll
  for (int i = 0; i < 4; i++)
#pragma unroll
    for (int j = 0; j < 8; j++)
#pragma unroll
      for (int q = 0; q < 4; q++) acc[i][j][q] = 0.f;

  const int NC = K / BK;

  auto issue = [&](int s, int c) {
    if (c < NC) {
      const uint32_t d = smb + (uint32_t)s * STAGE_BYTES +
                         (uint32_t)(row0 * 128) + swc16;
      const size_t koff = (size_t)c * BK;
#pragma unroll
      for (int it = 0; it < 8; it++) {  // A: 256 rows
        cp16(d + OFF_AH + it * 4096, aHp + koff + it * rstep);
        cp16(d + OFF_AL + it * 4096, aLp + koff + it * rstep);
      }
#pragma unroll
      for (int it = 0; it < 4; it++) {  // B: 128 rows
        cp16(d + OFF_BH + it * 4096, bHp + koff + it * rstep);
        cp16(d + OFF_BL + it * 4096, bLp + koff + it * rstep);
      }
    }
    cp_commit();  // always commit (possibly empty) so wait_group counts advance
  };

  issue(0, 0);
  issue(1, 1);

  const int lr  = lane & 15;
  const int lc8 = lane >> 4;

  // per-warp smem row byte offsets (swizzle xor handled via kx)
  uint32_t arow[4], brow[4];
#pragma unroll
  for (int i = 0; i < 4; i++) arow[i] = (uint32_t)((wm * 64 + i * 16 + lr) * 128);
#pragma unroll
  for (int j = 0; j < 4; j++) brow[j] = (uint32_t)((wn * 64 + j * 16 + lr) * 128);

  for (int c = 0; c < NC; c++) {
    cp_wait<1>();
    __syncthreads();

    const uint32_t sS = smb + (uint32_t)(c & 1) * STAGE_BYTES;
#pragma unroll
    for (int ks = 0; ks < 4; ks++) {
      const uint32_t kx = (uint32_t)(((ks * 2 + lc8) ^ (lr & 7)) * 16);
      uint32_t ah[4][4], al[4][4];
#pragma unroll
      for (int i = 0; i < 4; i++) {
        uint32_t ad = sS + arow[i] + kx;
        ldsm4(ah[i], ad + OFF_AH);
        ldsm4(al[i], ad + OFF_AL);
      }
      uint32_t bhA[4], blA[4], bhB[4], blB[4];
      {
        uint32_t bd = sS + brow[0] + kx;
        ldsm4(bhA, bd + OFF_BH);
        ldsm4(blA, bd + OFF_BL);
      }
#pragma unroll
      for (int j = 0; j < 4; j++) {
        uint32_t* bh = (j & 1) ? bhB : bhA;
        uint32_t* bl = (j & 1) ? blB : blA;
        if (j < 3) {  // prefetch next j's B fragments under this j's MMAs
          uint32_t bd = sS + brow[j + 1] + kx;
          ldsm4((j & 1) ? bhA : bhB, bd + OFF_BH);
          ldsm4((j & 1) ? blA : blB, bd + OFF_BL);
        }
        // pass 1: Ah*Bh
#pragma unroll
        for (int i = 0; i < 4; i++) {
          mma16816(acc[i][2 * j + 0], ah[i], bh[0], bh[2]);
          mma16816(acc[i][2 * j + 1], ah[i], bh[1], bh[3]);
        }
        // pass 2: Ah*Bl
#pragma unroll
        for (int i = 0; i < 4; i++) {
          mma16816(acc[i][2 * j + 0], ah[i], bl[0], bl[2]);
          mma16816(acc[i][2 * j + 1], ah[i], bl[1], bl[3]);
        }
        // pass 3: Al*Bh
#pragma unroll
        for (int i = 0; i < 4; i++) {
          mma16816(acc[i][2 * j + 0], al[i], bh[0], bh[2]);
          mma16816(acc[i][2 * j + 1], al[i], bh[1], bh[3]);
        }
      }
    }
    __syncthreads();
    issue(c & 1, c + 2);
  }

  // Epilogue: warp writes its 64x64 block.
  const bool act = second;
#pragma unroll
  for (int i = 0; i < 4; i++) {
    int r0 = m0 + wm * 64 + i * 16 + (lane >> 2);
#pragma unroll
    for (int j = 0; j < 8; j++) {
      int col = n0 + wn * 64 + j * 8 + (lane & 3) * 2;
      float b0 = bias[col], b1 = bias[col + 1];
      float v0 = acc[i][j][0] + b0;
      float v1 = acc[i][j][1] + b1;
      float v2 = acc[i][j][2] + b0;
      float v3 = acc[i][j][3] + b1;
      if (act) {
        v0 = 1.f / (1.f + expf(-v0));
        v1 = 1.f / (1.f + expf(-v1));
        v2 = 1.f / (1.f + expf(-v2));
        v3 = 1.f / (1.f + expf(-v3));
      }
      *reinterpret_cast<float2*>(&C[(size_t)r0 * N + col])       = make_float2(v0, v1);
      *reinterpret_cast<float2*>(&C[(size_t)(r0 + 8) * N + col]) = make_float2(v2, v3);
    }
  }
}

// ---------------------------------------------------------------------------
// Elementwise fp32 -> bf16 hi/lo split (float4 per thread).
// ---------------------------------------------------------------------------
__global__ __launch_bounds__(256) void split_kernel(
    const float* __restrict__ src, __nv_bfloat16* __restrict__ hi,
    __nv_bfloat16* __restrict__ lo, int n4) {
  int i = blockIdx.x * blockDim.x + threadIdx.x;
  if (i >= n4) return;
  float4 v = reinterpret_cast<const float4*>(src)[i];
  uint32_t h0, l0, h1, l1;
  split2(v.x, v.y, h0, l0);
  split2(v.z, v.w, h1, l1);
  reinterpret_cast<uint2*>(hi)[i] = make_uint2(h0, h1);
  reinterpret_cast<uint2*>(lo)[i] = make_uint2(l0, l1);
}

// ---------------------------------------------------------------------------
// Scan: h_t = a*h_{t-1} + u_t; p_t = h_t*g_t written as bf16 hi/lo.
// ---------------------------------------------------------------------------
__global__ __launch_bounds__(256) void scan_gate_kernel(
    const float* __restrict__ log_a) {
  int idx = blockIdx.x * blockDim.x + threadIdx.x;
  int b = idx / HH;
  int h = idx % HH;
  float a = 1.f / (1.f + expf(-log_a[h]));
  float hs = 0.f;

  const float* up = g_u + (size_t)b * Tt * HH + h;
  const float* gp = g_g + (size_t)b * Tt * HH + h;
  __nv_bfloat16* ph = g_ph + (size_t)b * Tt * HH + h;
  __nv_bfloat16* pl = g_pl + (size_t)b * Tt * HH + h;

  for (int t0 = 0; t0 < Tt; t0 += 16) {
    float uu[16], gg[16];
#pragma unroll
    for (int i = 0; i < 16; i++) {
      uu[i] = up[(size_t)(t0 + i) * HH];
      gg[i] = gp[(size_t)(t0 + i) * HH];
    }
#pragma unroll
    for (int i = 0; i < 16; i++) {
      hs = fmaf(a, hs, uu[i]);
      float p = hs * gg[i];
      __nv_bfloat16 hb = __float2bfloat16_rn(p);
      ph[(size_t)(t0 + i) * HH] = hb;
      pl[(size_t)(t0 + i) * HH] = __float2bfloat16_rn(p - __bfloat162float(hb));
    }
  }
}

// ---------------------------------------------------------------------------
extern "C" void kernel_launch(void* const* d_in, const int* in_sizes, int n_in,
                              void* d_out, int out_size) {
  const float* x     = (const float*)d_in[0];
  const float* Wi    = (const float*)d_in[1];
  const float* bi    = (const float*)d_in[2];
  const float* Wg    = (const float*)d_in[3];
  const float* bg    = (const float*)d_in[4];
  const float* Wo    = (const float*)d_in[5];
  const float* bo    = (const float*)d_in[6];
  const float* log_a = (const float*)d_in[7];
  float* y = (float*)d_out;

  float *u_p, *g_p;
  __nv_bfloat16 *xh, *xl, *ph, *pl, *wih, *wil, *wgh, *wgl, *woh, *wol;
  cudaGetSymbolAddress((void**)&u_p, g_u);
  cudaGetSymbolAddress((void**)&g_p, g_g);
  cudaGetSymbolAddress((void**)&xh, g_xh);
  cudaGetSymbolAddress((void**)&xl, g_xl);
  cudaGetSymbolAddress((void**)&ph, g_ph);
  cudaGetSymbolAddress((void**)&pl, g_pl);
  cudaGetSymbolAddress((void**)&wih, g_wih);
  cudaGetSymbolAddress((void**)&wil, g_wil);
  cudaGetSymbolAddress((void**)&wgh, g_wgh);
  cudaGetSymbolAddress((void**)&wgl, g_wgl);
  cudaGetSymbolAddress((void**)&woh, g_woh);
  cudaGetSymbolAddress((void**)&wol, g_wol);

  cudaFuncSetAttribute(gemm_bf16s, cudaFuncAttributeMaxDynamicSharedMemorySize,
                       SMEM_BYTES);

  // Pre-split inputs
  int n4x = Mrows * DIN / 4;
  int n4w = HH * DIN / 4;
  split_kernel<<<n4x / 256, 256>>>(x, xh, xl, n4x);
  split_kernel<<<n4w / 256, 256>>>(Wi, wih, wil, n4w);
  split_kernel<<<n4w / 256, 256>>>(Wg, wgh, wgl, n4w);
  split_kernel<<<n4w / 256, 256>>>(Wo, woh, wol, n4w);

  dim3 blk(256);
  // Fused u + gate GEMM: 16 n-tiles for u (no act), 16 for gate (sigmoid).
  gemm_bf16s<<<dim3(32, Mrows / BM), blk, SMEM_BYTES>>>(
      xh, xl, wih, wil, bi, u_p, wgh, wgl, bg, g_p, 16, HH, DIN);

  scan_gate_kernel<<<(Bb * HH) / 256, 256>>>(log_a);

  // Output GEMM: all 8 n-tiles in set 1 (no act).
  gemm_bf16s<<<dim3(8, Mrows / BM), blk, SMEM_BYTES>>>(
      ph, pl, woh, wol, bo, y, woh, wol, bo, y, 8, DIN, HH);
}